// round 2
// baseline (speedup 1.0000x reference)
#include <cuda_runtime.h>

// QuantumLayer: the full 8-qubit circuit collapses analytically to
//   out[b] = cos(x[b,0] + weights[0])
// Proof sketch:
//  - RY layers on |0> compose: RY(w)RY(x)|0> = RY(x+w)|0>, product state.
//  - Qubit 0 is only a CNOT *control*; Z_0 commutes with CNOT(0,1), and the
//    rest of the chain acts on qubits >= 1. So P(q0) is unchanged by CNOTs.
//  - <Z_0> = cos^2(t/2) - sin^2(t/2) = cos(t), t = x[b,0] + w[0].
//
// Memory-bound: 8 MB effective read (stride-8 -> one float per 32B sector)
// + 1 MB write.

__global__ __launch_bounds__(256)
void quantum_layer_kernel(const float* __restrict__ x,
                          const float* __restrict__ w,
                          float* __restrict__ out,
                          int B)
{
    const float w0 = __ldg(w);  // broadcast, L2/L1 cached
    int base = (blockIdx.x * blockDim.x + threadIdx.x) * 4;
    if (base + 3 < B) {
        // 4 independent stride-8 loads -> MLP=4 per thread
        float a0 = __ldg(&x[(size_t)(base + 0) * 8]);
        float a1 = __ldg(&x[(size_t)(base + 1) * 8]);
        float a2 = __ldg(&x[(size_t)(base + 2) * 8]);
        float a3 = __ldg(&x[(size_t)(base + 3) * 8]);
        float4 r;
        r.x = cosf(a0 + w0);
        r.y = cosf(a1 + w0);
        r.z = cosf(a2 + w0);
        r.w = cosf(a3 + w0);
        *reinterpret_cast<float4*>(&out[base]) = r;
    } else {
        // tail (not hit for B=262144, kept for safety)
        for (int b = base; b < B; ++b) {
            out[b] = cosf(__ldg(&x[(size_t)b * 8]) + w0);
        }
    }
}

extern "C" void kernel_launch(void* const* d_in, const int* in_sizes, int n_in,
                              void* d_out, int out_size)
{
    const float* x = (const float*)d_in[0];   // [B, 8] float32
    const float* w = (const float*)d_in[1];   // [8]   float32
    float* out = (float*)d_out;               // [B]   float32
    int B = out_size;

    int threads = 256;
    int work = (B + 3) / 4;
    int blocks = (work + threads - 1) / threads;
    quantum_layer_kernel<<<blocks, threads>>>(x, w, out, B);
}

// round 3
// speedup vs baseline: 1.1490x; 1.1490x over previous
#include <cuda_runtime.h>

// QuantumLayer collapses analytically to out[b] = cos(x[b,0] + weights[0]):
//  - RY(w)RY(x)|0> = RY(x+w)|0> (product state, angles add).
//  - Qubit 0 is only ever a CNOT control; Z_0 commutes with CNOT(0,1) and the
//    rest of the chain touches qubits >= 1, so <Z_0> is unchanged.
//  - <Z_0> = cos^2(t/2) - sin^2(t/2) = cos(t).
//
// Each 8-float row of x is exactly one 32B sector, so minimal DRAM traffic is
// the whole 8 MB of x + 1 MB out, fixed. Optimization target is wave balance
// (1024 CTAs ~ 6.92/SM, ~1% tail vs the previous 256-CTA 2x tail) and per-SM
// L1tex wavefront drain (~1/cyc): floor ~2000 cyc/SM ~= 1.1 us.

__global__ __launch_bounds__(256)
void quantum_layer_kernel(const float* __restrict__ x,
                          const float* __restrict__ w,
                          float* __restrict__ out,
                          int B)
{
    const float w0 = __ldg(w);
    int b = blockIdx.x * blockDim.x + threadIdx.x;
    if (b < B) {
        // streaming load: one 32B sector per row, no reuse
        float a;
        asm volatile("ld.global.cs.f32 %0, [%1];"
                     : "=f"(a) : "l"(x + (size_t)b * 8));
        float r = __cosf(a + w0);
        asm volatile("st.global.cs.f32 [%0], %1;"
                     :: "l"(out + b), "f"(r) : "memory");
    }
}

extern "C" void kernel_launch(void* const* d_in, const int* in_sizes, int n_in,
                              void* d_out, int out_size)
{
    const float* x = (const float*)d_in[0];   // [B, 8] float32
    const float* w = (const float*)d_in[1];   // [8]   float32
    float* out = (float*)d_out;               // [B]   float32
    int B = out_size;

    int threads = 256;
    int blocks = (B + threads - 1) / threads;  // 1024 for B=262144
    quantum_layer_kernel<<<blocks, threads>>>(x, w, out, B);
}